// round 5
// baseline (speedup 1.0000x reference)
#include <cuda_runtime.h>

#define FULLMASK 0xFFFFFFFFu
constexpr int Bb = 4, Nn = 384, Dd = 64;
constexpr int NR = Bb * Nn;
constexpr int GRAM_BLOCKS = Bb * 12 * 12;   // 576 (32x32 tiles)
constexpr int ROW_BLOCKS = NR / 8;          // 192

__device__ float g_y2[NR];
__device__ float g_uself[NR * Dd];
__device__ float g_ci[NR * Dd];    // stored PRE-HALVED
__device__ float g_P[NR * Dd];     // stored PRE-HALVED
__device__ float g_gram[(size_t)Bb * Nn * Nn];

__device__ __forceinline__ float wred(float v) {
  #pragma unroll
  for (int o = 16; o > 0; o >>= 1) v += __shfl_xor_sync(FULLMASK, v, o);
  return v;
}
__device__ __forceinline__ float sigm(float x) { return 1.f / (1.f + __expf(-x)); }
__device__ __forceinline__ float silu_(float x) { return x * sigm(x); }
__device__ __forceinline__ float artanh_(float x) {
  x = fminf(x, 1.f - 1e-7f);
  return 0.5f * (log1pf(x) - log1pf(-x));
}
__device__ __forceinline__ float tfa(float x) {
  float y; asm("tanh.approx.f32 %0, %1;" : "=f"(y) : "f"(x)); return y;
}

// ===== k_pre: blocks [0,576) = gram 32x32 tiles; [576,768) = row precompute =====
__global__ __launch_bounds__(256)
void k_pre(const float* __restrict__ x,
           const float* __restrict__ att_w1,
           const float* __restrict__ att_b1)
{
  const int tid = threadIdx.x, w = tid >> 5, lane = tid & 31;

  if (blockIdx.x < GRAM_BLOCKS) {
    __shared__ float xis[32][65], xjs[32][65];
    const int t = blockIdx.x;
    const int b = t / 144, rr = t % 144, it = rr / 12, jt = rr % 12;
    const float* xb = x + (size_t)b * Nn * 64;
    for (int e = tid; e < 2048; e += 256) {
      const int r = e >> 6, c = e & 63;
      xis[r][c] = xb[(size_t)(it * 32 + r) * 64 + c];
      xjs[r][c] = xb[(size_t)(jt * 32 + r) * 64 + c];
    }
    __syncthreads();
    const int jj = lane, i4 = w * 4;
    float a0 = 0.f, a1 = 0.f, a2 = 0.f, a3 = 0.f;
    #pragma unroll 16
    for (int k = 0; k < 64; ++k) {
      const float xv = xjs[jj][k];
      a0 = fmaf(xis[i4 + 0][k], xv, a0);
      a1 = fmaf(xis[i4 + 1][k], xv, a1);
      a2 = fmaf(xis[i4 + 2][k], xv, a2);
      a3 = fmaf(xis[i4 + 3][k], xv, a3);
    }
    float* go = g_gram + ((size_t)(b * Nn) + it * 32 + i4) * Nn + jt * 32 + jj;
    go[0] = a0; go[Nn] = a1; go[2 * Nn] = a2; go[3 * Nn] = a3;
    return;
  }

  // ---- row precompute: 8 rows/block ----
  __shared__ float xis8[8][64];
  __shared__ float us[8][64];
  const int idx = blockIdx.x - GRAM_BLOCKS;
  const int b = idx / 48, i0 = (idx % 48) * 8;
  const float* xb = x + (size_t)b * Nn * 64;

  for (int t = tid; t < 512; t += 256)
    xis8[t >> 6][t & 63] = xb[(size_t)(i0 + (t >> 6)) * 64 + (t & 63)];
  __syncthreads();

  {
    const int r = w, gi = b * Nn + i0 + r;
    const float a0 = xis8[r][lane], a1 = xis8[r][lane + 32];
    const float x2 = wred(a0 * a0 + a1 * a1);
    const float A = 1.f - 2.f * x2 + x2;
    const float Bc = 1.f - x2;
    const float den = fmaxf(1.f - 2.f * x2 + x2 * x2, 1e-15f);
    const float inv = 1.f / den;
    const float s0 = (A * (-a0) + Bc * a0) * inv;
    const float s1 = (A * (-a1) + Bc * a1) * inv;
    const float sn = fmaxf(sqrtf(wred(s0 * s0 + s1 * s1)), 1e-15f);
    const float fac = fmaxf(Bc, 1e-15f);
    const float g = fac * artanh_(sn) / sn;
    us[r][lane] = g * s0; us[r][lane + 32] = g * s1;
    g_uself[(size_t)gi * 64 + lane] = g * s0;
    g_uself[(size_t)gi * 64 + lane + 32] = g * s1;
    if (!lane) g_y2[gi] = x2;
  }
  __syncthreads();

  {
    const int k = tid & 63, rp = tid >> 6;     // rows rp, rp+4
    float p0 = 0.f, p1 = 0.f, c0 = att_b1[k], c1v = att_b1[k];
    #pragma unroll 8
    for (int d = 0; d < 64; ++d) {
      const float wa = att_w1[d * 64 + k];
      const float wb = att_w1[(64 + d) * 64 + k];
      p0 = fmaf(xis8[rp][d], wa, p0);
      p1 = fmaf(xis8[rp + 4][d], wa, p1);
      c0 = fmaf(us[rp][d], wb, c0);
      c1v = fmaf(us[rp + 4][d], wb, c1v);
    }
    const int g0 = b * Nn + i0 + rp, g1 = g0 + 4;
    g_P[(size_t)g0 * 64 + k] = 0.5f * p0;   // pre-halved for silu trick
    g_P[(size_t)g1 * 64 + k] = 0.5f * p1;
    g_ci[(size_t)g0 * 64 + k] = 0.5f * c0;
    g_ci[(size_t)g1 * 64 + k] = 0.5f * c1v;
  }
}

// ============ k_main: 4 rows/block, lane-parallel edges ============
__global__ __launch_bounds__(256)
void k_main(const float* __restrict__ x,
            const int* __restrict__ mask,
            const float* __restrict__ att_w2,
            const float* __restrict__ att_b2,
            const float* __restrict__ mlp_w1,
            const float* __restrict__ mlp_b1,
            const float* __restrict__ mlp_w2,
            const float* __restrict__ mlp_b2,
            float* __restrict__ out)
{
  __shared__ __align__(16) float Pt[64 * 129];
  __shared__ float4 cpw[4][64];
  __shared__ float wkj[4][Nn];
  __shared__ unsigned short wji[4][Nn];
  __shared__ unsigned char jidx[4][128];
  __shared__ int mcnt[4], mbase[4];
  __shared__ float s1p[8];

  const int tid = threadIdx.x, w = tid >> 5, lane = tid & 31;
  const int ct = blockIdx.x;
  const int b = ct / 96, i0 = (ct % 96) * 4;
  const int r = w & 3;
  const int gi = b * Nn + i0 + r;

  {
    const int rr = tid >> 6, k = tid & 63;
    const int gr_ = b * Nn + i0 + rr;
    cpw[rr][k] = make_float4(g_ci[(size_t)gr_ * 64 + k],
                             g_P[(size_t)gr_ * 64 + k], att_w2[k], 0.f);
  }
  if (tid < 4) mbase[tid] = 0;
  __syncthreads();

  const float x2i = g_y2[gi];
  const float omx2 = 1.f - x2i;
  const float fac = fmaxf(omx2, 1e-15f);
  const float b2v = att_b2[0];
  float S1 = 0.f;

  const float4* cp4 = cpw[r];
  const float* Pbat = g_P + (size_t)(b * Nn) * 64;

  for (int jt = 0; jt < 3; ++jt) {
    const int j0 = jt * 128;
    __syncthreads();
    for (int t = tid; t < 8192; t += 256) {
      const int j = t >> 6, k = t & 63;
      Pt[k * 129 + j] = Pbat[(size_t)(j0 + j) * 64 + k];
    }
    if (w < 4) {
      const int* mrow = mask + (size_t)(b * Nn + i0 + w) * Nn + j0;
      int m = 0;
      #pragma unroll
      for (int sub = 0; sub < 4; ++sub) {
        const bool ok = mrow[sub * 32 + lane] != 0;
        const unsigned bal = __ballot_sync(FULLMASK, ok);
        const unsigned pre = bal & ((1u << lane) - 1u);
        if (ok) jidx[w][m + __popc(pre)] = (unsigned char)(sub * 32 + lane);
        m += __popc(bal);
      }
      if (!lane) mcnt[w] = m;
    }
    __syncthreads();

    const int m = mcnt[r];
    const int mb = mbase[r];
    const float* grow = g_gram + (size_t)gi * Nn + j0;
    const float* y2row = g_y2 + b * Nn + j0;

    for (int g = (w >> 2); g * 32 < m; g += 2) {
      const int idx = g * 32 + lane;
      const bool val = idx < m;
      const int jj = val ? jidx[r][idx] : 0;
      float c1 = 0.f, c2 = 0.f;
      if (val) {
        const float xy = grow[jj], y2v = y2row[jj];
        const float A = 1.f - 2.f * xy + y2v;
        const float den = fmaxf(fmaf(x2i, y2v, 1.f - 2.f * xy), 1e-15f);
        const float inv = __frcp_rn(den);
        const float t1 = fmaf(A, x2i, -omx2 * xy);
        const float t2 = fmaf(omx2, y2v, -A * xy);
        float sn = sqrtf(fmaxf(inv * inv * fmaf(A, t1, omx2 * t2), 0.f));
        sn = fminf(fmaxf(sn, 1e-15f), 1.f - 1e-7f);
        const float aos = (sn > 1e-3f)
            ? __fdividef(0.5f * __logf((1.f + sn) * __frcp_rn(1.f - sn)), sn)
            : fmaf(sn * sn, 0.33333334f, 1.f);
        const float gg = fac * aos * inv;
        c1 = -gg * A; c2 = gg * omx2;
      }
      // pr = sum_k silu(h_k)*w2_k ; h/2 = cp.x + c1*cp.y + c2*Pt (all pre-halved)
      float p0 = 0.f, p1 = 0.f, p2 = 0.f, p3 = 0.f;
      #pragma unroll
      for (int k = 0; k < 64; k += 4) {
        {
          const float4 cp = cp4[k];
          const float t = fmaf(c2, Pt[k * 129 + jj], fmaf(c1, cp.y, cp.x));
          p0 = fmaf(fmaf(t, tfa(t), t), cp.z, p0);
        }
        {
          const float4 cp = cp4[k + 1];
          const float t = fmaf(c2, Pt[(k + 1) * 129 + jj], fmaf(c1, cp.y, cp.x));
          p1 = fmaf(fmaf(t, tfa(t), t), cp.z, p1);
        }
        {
          const float4 cp = cp4[k + 2];
          const float t = fmaf(c2, Pt[(k + 2) * 129 + jj], fmaf(c1, cp.y, cp.x));
          p2 = fmaf(fmaf(t, tfa(t), t), cp.z, p2);
        }
        {
          const float4 cp = cp4[k + 3];
          const float t = fmaf(c2, Pt[(k + 3) * 129 + jj], fmaf(c1, cp.y, cp.x));
          p3 = fmaf(fmaf(t, tfa(t), t), cp.z, p3);
        }
      }
      const float pr = (p0 + p1) + (p2 + p3);
      const float att = fmaf(0.5f, tfa(0.5f * (pr + b2v)), 0.5f);
      S1 = fmaf(att, c1, S1);
      if (val) {
        wkj[r][mb + idx] = att * c2;
        wji[r][mb + idx] = (unsigned short)(j0 + jj);
      }
    }
    __syncthreads();
    if (tid < 4) mbase[tid] += mcnt[tid];
  }
  {
    const float s = wred(S1);
    if (!lane) s1p[w] = s;
  }
  __syncthreads();

  float* tailbuf = Pt;
  float* supv = tailbuf;
  float* hm2  = tailbuf + 256;
  float* ot   = tailbuf + 512;

  // support: 4-way unrolled independent chains
  {
    const int i2 = tid >> 6, d = tid & 63;
    const int gr_ = b * Nn + i0 + i2;
    const float* xb = x + (size_t)(b * Nn) * 64;
    const int mt = mbase[i2];
    float a0 = 0.f, a1 = 0.f, a2 = 0.f, a3 = 0.f;
    int p = 0;
    for (; p + 4 <= mt; p += 4) {
      a0 = fmaf(wkj[i2][p],     xb[(size_t)wji[i2][p]     * 64 + d], a0);
      a1 = fmaf(wkj[i2][p + 1], xb[(size_t)wji[i2][p + 1] * 64 + d], a1);
      a2 = fmaf(wkj[i2][p + 2], xb[(size_t)wji[i2][p + 2] * 64 + d], a2);
      a3 = fmaf(wkj[i2][p + 3], xb[(size_t)wji[i2][p + 3] * 64 + d], a3);
    }
    for (; p < mt; ++p)
      a0 = fmaf(wkj[i2][p], xb[(size_t)wji[i2][p] * 64 + d], a0);
    const float S1t = s1p[i2] + s1p[i2 + 4];
    supv[i2 * 64 + d] = fmaf(S1t, x[(size_t)gr_ * 64 + d],
                             (a0 + a1) + (a2 + a3));
  }
  __syncthreads();

  {
    const int i2 = tid >> 6, k = tid & 63;
    const int gr_ = b * Nn + i0 + i2;
    float acc = mlp_b1[k];
    #pragma unroll 8
    for (int d = 0; d < 64; ++d)
      acc = fmaf(g_uself[(size_t)gr_ * 64 + d], mlp_w1[d * 64 + k], acc);
    #pragma unroll 8
    for (int d = 0; d < 64; ++d)
      acc = fmaf(supv[i2 * 64 + d], mlp_w1[(64 + d) * 64 + k], acc);
    hm2[i2 * 64 + k] = silu_(acc);
  }
  __syncthreads();
  {
    const int i2 = tid >> 6, k = tid & 63;
    const int gr_ = b * Nn + i0 + i2;
    float o = mlp_b2[k] + g_uself[(size_t)gr_ * 64 + k];
    #pragma unroll 8
    for (int d = 0; d < 64; ++d)
      o = fmaf(hm2[i2 * 64 + d], mlp_w2[d * 64 + k], o);
    ot[i2 * 64 + k] = o;
  }
  __syncthreads();

  if (w < 4) {
    const int gr_ = b * Nn + i0 + w;
    const float a0 = x[(size_t)gr_ * 64 + lane], a1 = x[(size_t)gr_ * 64 + lane + 32];
    const float xx2 = g_y2[gr_];
    const float o0 = ot[w * 64 + lane], o1 = ot[w * 64 + lane + 32];
    const float un = fmaxf(sqrtf(wred(o0 * o0 + o1 * o1)), 1e-15f);
    const float lam = 2.f / fmaxf(1.f - xx2, 1e-15f);
    const float th = tanhf(0.5f * lam * un);
    const float sc = th / un;
    const float sec0 = sc * o0, sec1 = sc * o1;
    const float xy = wred(a0 * sec0 + a1 * sec1);
    const float y2 = wred(sec0 * sec0 + sec1 * sec1);
    const float A = 1.f + 2.f * xy + y2;
    const float Bc = 1.f - xx2;
    const float den = fmaxf(1.f + 2.f * xy + xx2 * y2, 1e-15f);
    const float inv = 1.f / den;
    float r0 = (A * a0 + Bc * sec0) * inv;
    float r1 = (A * a1 + Bc * sec1) * inv;
    const float nrm = fmaxf(sqrtf(wred(r0 * r0 + r1 * r1)), 1e-15f);
    if (nrm > 0.996f) { const float s = 0.996f / nrm; r0 *= s; r1 *= s; }
    float* orow = out + (size_t)gr_ * 64;
    orow[lane] = r0; orow[lane + 32] = r1;
  }
}

extern "C" void kernel_launch(void* const* d_in, const int* in_sizes, int n_in,
                              void* d_out, int out_size)
{
  const float* x      = (const float*)d_in[0];
  const int*   mask   = (const int*)d_in[1];
  const float* att_w1 = (const float*)d_in[2];
  const float* att_b1 = (const float*)d_in[3];
  const float* att_w2 = (const float*)d_in[4];
  const float* att_b2 = (const float*)d_in[5];
  const float* mlp_w1 = (const float*)d_in[6];
  const float* mlp_b1 = (const float*)d_in[7];
  const float* mlp_w2 = (const float*)d_in[8];
  const float* mlp_b2 = (const float*)d_in[9];
  float* out = (float*)d_out;

  k_pre<<<GRAM_BLOCKS + ROW_BLOCKS, 256>>>(x, att_w1, att_b1);
  k_main<<<Bb * (Nn / 4), 256>>>(x, mask, att_w2, att_b2,
                                 mlp_w1, mlp_b1, mlp_w2, mlp_b2, out);
}

// round 6
// speedup vs baseline: 1.6768x; 1.6768x over previous
#include <cuda_runtime.h>

#define FULLMASK 0xFFFFFFFFu
constexpr int Bb = 4, Nn = 384, Dd = 64;
constexpr int NR = Bb * Nn;
constexpr int GRAM_BLOCKS = Bb * 12 * 12;   // 576 (32x32 tiles)
constexpr int ROW_BLOCKS = NR / 8;          // 192

__device__ float g_y2[NR];
__device__ float g_uself[NR * Dd];
__device__ float g_ci[NR * Dd];    // stored PRE-HALVED
__device__ float g_P[NR * Dd];     // stored PRE-HALVED
__device__ float g_gram[(size_t)Bb * Nn * Nn];

__device__ __forceinline__ float wred(float v) {
  #pragma unroll
  for (int o = 16; o > 0; o >>= 1) v += __shfl_xor_sync(FULLMASK, v, o);
  return v;
}
__device__ __forceinline__ float sigm(float x) { return 1.f / (1.f + __expf(-x)); }
__device__ __forceinline__ float silu_(float x) { return x * sigm(x); }
__device__ __forceinline__ float artanh_(float x) {
  x = fminf(x, 1.f - 1e-7f);
  return 0.5f * (log1pf(x) - log1pf(-x));
}
__device__ __forceinline__ float tfa(float x) {
  float y; asm("tanh.approx.f32 %0, %1;" : "=f"(y) : "f"(x)); return y;
}

// ===== k_pre: blocks [0,576) = gram 32x32 tiles; [576,768) = row precompute =====
__global__ __launch_bounds__(256)
void k_pre(const float* __restrict__ x,
           const float* __restrict__ att_w1,
           const float* __restrict__ att_b1)
{
  const int tid = threadIdx.x, w = tid >> 5, lane = tid & 31;

  if (blockIdx.x < GRAM_BLOCKS) {
    __shared__ float xis[32][65], xjs[32][65];
    const int t = blockIdx.x;
    const int b = t / 144, rr = t % 144, it = rr / 12, jt = rr % 12;
    const float* xb = x + (size_t)b * Nn * 64;
    for (int e = tid; e < 2048; e += 256) {
      const int r = e >> 6, c = e & 63;
      xis[r][c] = xb[(size_t)(it * 32 + r) * 64 + c];
      xjs[r][c] = xb[(size_t)(jt * 32 + r) * 64 + c];
    }
    __syncthreads();
    const int jj = lane, i4 = w * 4;
    float a0 = 0.f, a1 = 0.f, a2 = 0.f, a3 = 0.f;
    #pragma unroll 16
    for (int k = 0; k < 64; ++k) {
      const float xv = xjs[jj][k];
      a0 = fmaf(xis[i4 + 0][k], xv, a0);
      a1 = fmaf(xis[i4 + 1][k], xv, a1);
      a2 = fmaf(xis[i4 + 2][k], xv, a2);
      a3 = fmaf(xis[i4 + 3][k], xv, a3);
    }
    float* go = g_gram + ((size_t)(b * Nn) + it * 32 + i4) * Nn + jt * 32 + jj;
    go[0] = a0; go[Nn] = a1; go[2 * Nn] = a2; go[3 * Nn] = a3;
    return;
  }

  // ---- row precompute: 8 rows/block ----
  __shared__ float xis8[8][64];
  __shared__ float us[8][64];
  const int idx = blockIdx.x - GRAM_BLOCKS;
  const int b = idx / 48, i0 = (idx % 48) * 8;
  const float* xb = x + (size_t)b * Nn * 64;

  for (int t = tid; t < 512; t += 256)
    xis8[t >> 6][t & 63] = xb[(size_t)(i0 + (t >> 6)) * 64 + (t & 63)];
  __syncthreads();

  {
    const int r = w, gi = b * Nn + i0 + r;
    const float a0 = xis8[r][lane], a1 = xis8[r][lane + 32];
    const float x2 = wred(a0 * a0 + a1 * a1);
    const float A = 1.f - 2.f * x2 + x2;
    const float Bc = 1.f - x2;
    const float den = fmaxf(1.f - 2.f * x2 + x2 * x2, 1e-15f);
    const float inv = 1.f / den;
    const float s0 = (A * (-a0) + Bc * a0) * inv;
    const float s1 = (A * (-a1) + Bc * a1) * inv;
    const float sn = fmaxf(sqrtf(wred(s0 * s0 + s1 * s1)), 1e-15f);
    const float fac = fmaxf(Bc, 1e-15f);
    const float g = fac * artanh_(sn) / sn;
    us[r][lane] = g * s0; us[r][lane + 32] = g * s1;
    g_uself[(size_t)gi * 64 + lane] = g * s0;
    g_uself[(size_t)gi * 64 + lane + 32] = g * s1;
    if (!lane) g_y2[gi] = x2;
  }
  __syncthreads();

  {
    const int k = tid & 63, rp = tid >> 6;     // rows rp, rp+4
    float p0 = 0.f, p1 = 0.f, c0 = att_b1[k], c1v = att_b1[k];
    #pragma unroll 8
    for (int d = 0; d < 64; ++d) {
      const float wa = att_w1[d * 64 + k];
      const float wb = att_w1[(64 + d) * 64 + k];
      p0 = fmaf(xis8[rp][d], wa, p0);
      p1 = fmaf(xis8[rp + 4][d], wa, p1);
      c0 = fmaf(us[rp][d], wb, c0);
      c1v = fmaf(us[rp + 4][d], wb, c1v);
    }
    const int g0 = b * Nn + i0 + rp, g1 = g0 + 4;
    g_P[(size_t)g0 * 64 + k] = 0.5f * p0;   // pre-halved for silu trick
    g_P[(size_t)g1 * 64 + k] = 0.5f * p1;
    g_ci[(size_t)g0 * 64 + k] = 0.5f * c0;
    g_ci[(size_t)g1 * 64 + k] = 0.5f * c1v;
  }
}

// ============ k_main: 4 rows/block, lane-parallel edges ============
__global__ __launch_bounds__(256, 3)
void k_main(const float* __restrict__ x,
            const int* __restrict__ mask,
            const float* __restrict__ att_w2,
            const float* __restrict__ att_b2,
            const float* __restrict__ mlp_w1,
            const float* __restrict__ mlp_b1,
            const float* __restrict__ mlp_w2,
            const float* __restrict__ mlp_b2,
            float* __restrict__ out)
{
  __shared__ __align__(16) float Pt[64 * 129];
  __shared__ float4 cpw[4][64];
  __shared__ float wkj[4][Nn];
  __shared__ unsigned short wji[4][Nn];
  __shared__ unsigned char jidx[4][128];
  __shared__ int mcnt[4], mbase[4];
  __shared__ float s1p[8];

  const int tid = threadIdx.x, w = tid >> 5, lane = tid & 31;
  const int ct = blockIdx.x;
  const int b = ct / 96, i0 = (ct % 96) * 4;
  const int r = w & 3;
  const int gi = b * Nn + i0 + r;

  {
    const int rr = tid >> 6, k = tid & 63;
    const int gr_ = b * Nn + i0 + rr;
    cpw[rr][k] = make_float4(g_ci[(size_t)gr_ * 64 + k],
                             g_P[(size_t)gr_ * 64 + k], att_w2[k], 0.f);
  }
  if (tid < 4) mbase[tid] = 0;
  __syncthreads();

  const float x2i = g_y2[gi];
  const float omx2 = 1.f - x2i;
  const float fac = fmaxf(omx2, 1e-15f);
  const float b2v = att_b2[0];
  float S1 = 0.f;

  const float4* cp4 = cpw[r];
  const float* Pbat = g_P + (size_t)(b * Nn) * 64;

  for (int jt = 0; jt < 3; ++jt) {
    const int j0 = jt * 128;
    __syncthreads();
    for (int t = tid; t < 8192; t += 256) {
      const int j = t >> 6, k = t & 63;
      Pt[k * 129 + j] = Pbat[(size_t)(j0 + j) * 64 + k];
    }
    if (w < 4) {
      const int* mrow = mask + (size_t)(b * Nn + i0 + w) * Nn + j0;
      int m = 0;
      #pragma unroll
      for (int sub = 0; sub < 4; ++sub) {
        const bool ok = mrow[sub * 32 + lane] != 0;
        const unsigned bal = __ballot_sync(FULLMASK, ok);
        const unsigned pre = bal & ((1u << lane) - 1u);
        if (ok) jidx[w][m + __popc(pre)] = (unsigned char)(sub * 32 + lane);
        m += __popc(bal);
      }
      if (!lane) mcnt[w] = m;
    }
    __syncthreads();

    const int m = mcnt[r];
    const int mb = mbase[r];
    const float* grow = g_gram + (size_t)gi * Nn + j0;
    const float* y2row = g_y2 + b * Nn + j0;

    for (int g = (w >> 2); g * 32 < m; g += 2) {
      const int idx = g * 32 + lane;
      const bool val = idx < m;
      const int jj = val ? jidx[r][idx] : 0;
      float c1 = 0.f, c2 = 0.f;
      if (val) {
        const float xy = grow[jj], y2v = y2row[jj];
        const float A = 1.f - 2.f * xy + y2v;
        const float den = fmaxf(fmaf(x2i, y2v, 1.f - 2.f * xy), 1e-15f);
        const float inv = __frcp_rn(den);
        const float t1 = fmaf(A, x2i, -omx2 * xy);
        const float t2 = fmaf(omx2, y2v, -A * xy);
        float sn = sqrtf(fmaxf(inv * inv * fmaf(A, t1, omx2 * t2), 0.f));
        sn = fminf(fmaxf(sn, 1e-15f), 1.f - 1e-7f);
        const float aos = (sn > 1e-3f)
            ? __fdividef(0.5f * __logf((1.f + sn) * __frcp_rn(1.f - sn)), sn)
            : fmaf(sn * sn, 0.33333334f, 1.f);
        const float gg = fac * aos * inv;
        c1 = -gg * A; c2 = gg * omx2;
      }
      // pr = sum_k silu(h_k)*w2_k ; h/2 = cp.x + c1*cp.y + c2*Pt (pre-halved)
      const float* ptj = Pt + jj;
      float p0 = 0.f, p1 = 0.f, p2 = 0.f, p3 = 0.f;
      #pragma unroll 2
      for (int k = 0; k < 64; k += 4) {
        {
          const float4 cp = cp4[k];
          const float t = fmaf(c2, ptj[k * 129], fmaf(c1, cp.y, cp.x));
          p0 = fmaf(fmaf(t, tfa(t), t), cp.z, p0);
        }
        {
          const float4 cp = cp4[k + 1];
          const float t = fmaf(c2, ptj[(k + 1) * 129], fmaf(c1, cp.y, cp.x));
          p1 = fmaf(fmaf(t, tfa(t), t), cp.z, p1);
        }
        {
          const float4 cp = cp4[k + 2];
          const float t = fmaf(c2, ptj[(k + 2) * 129], fmaf(c1, cp.y, cp.x));
          p2 = fmaf(fmaf(t, tfa(t), t), cp.z, p2);
        }
        {
          const float4 cp = cp4[k + 3];
          const float t = fmaf(c2, ptj[(k + 3) * 129], fmaf(c1, cp.y, cp.x));
          p3 = fmaf(fmaf(t, tfa(t), t), cp.z, p3);
        }
      }
      const float pr = (p0 + p1) + (p2 + p3);
      const float att = fmaf(0.5f, tfa(0.5f * (pr + b2v)), 0.5f);
      S1 = fmaf(att, c1, S1);
      if (val) {
        wkj[r][mb + idx] = att * c2;
        wji[r][mb + idx] = (unsigned short)(j0 + jj);
      }
    }
    __syncthreads();
    if (tid < 4) mbase[tid] += mcnt[tid];
  }
  {
    const float s = wred(S1);
    if (!lane) s1p[w] = s;
  }
  __syncthreads();

  float* tailbuf = Pt;
  float* supv = tailbuf;
  float* hm2  = tailbuf + 256;
  float* ot   = tailbuf + 512;

  // support: 4-way unrolled independent chains
  {
    const int i2 = tid >> 6, d = tid & 63;
    const int gr_ = b * Nn + i0 + i2;
    const float* xb = x + (size_t)(b * Nn) * 64;
    const int mt = mbase[i2];
    float a0 = 0.f, a1 = 0.f, a2 = 0.f, a3 = 0.f;
    int p = 0;
    for (; p + 4 <= mt; p += 4) {
      a0 = fmaf(wkj[i2][p],     xb[(size_t)wji[i2][p]     * 64 + d], a0);
      a1 = fmaf(wkj[i2][p + 1], xb[(size_t)wji[i2][p + 1] * 64 + d], a1);
      a2 = fmaf(wkj[i2][p + 2], xb[(size_t)wji[i2][p + 2] * 64 + d], a2);
      a3 = fmaf(wkj[i2][p + 3], xb[(size_t)wji[i2][p + 3] * 64 + d], a3);
    }
    for (; p < mt; ++p)
      a0 = fmaf(wkj[i2][p], xb[(size_t)wji[i2][p] * 64 + d], a0);
    const float S1t = s1p[i2] + s1p[i2 + 4];
    supv[i2 * 64 + d] = fmaf(S1t, x[(size_t)gr_ * 64 + d],
                             (a0 + a1) + (a2 + a3));
  }
  __syncthreads();

  {
    const int i2 = tid >> 6, k = tid & 63;
    const int gr_ = b * Nn + i0 + i2;
    float acc = mlp_b1[k];
    #pragma unroll 8
    for (int d = 0; d < 64; ++d)
      acc = fmaf(g_uself[(size_t)gr_ * 64 + d], mlp_w1[d * 64 + k], acc);
    #pragma unroll 8
    for (int d = 0; d < 64; ++d)
      acc = fmaf(supv[i2 * 64 + d], mlp_w1[(64 + d) * 64 + k], acc);
    hm2[i2 * 64 + k] = silu_(acc);
  }
  __syncthreads();
  {
    const int i2 = tid >> 6, k = tid & 63;
    const int gr_ = b * Nn + i0 + i2;
    float o = mlp_b2[k] + g_uself[(size_t)gr_ * 64 + k];
    #pragma unroll 8
    for (int d = 0; d < 64; ++d)
      o = fmaf(hm2[i2 * 64 + d], mlp_w2[d * 64 + k], o);
    ot[i2 * 64 + k] = o;
  }
  __syncthreads();

  if (w < 4) {
    const int gr_ = b * Nn + i0 + w;
    const float a0 = x[(size_t)gr_ * 64 + lane], a1 = x[(size_t)gr_ * 64 + lane + 32];
    const float xx2 = g_y2[gr_];
    const float o0 = ot[w * 64 + lane], o1 = ot[w * 64 + lane + 32];
    const float un = fmaxf(sqrtf(wred(o0 * o0 + o1 * o1)), 1e-15f);
    const float lam = 2.f / fmaxf(1.f - xx2, 1e-15f);
    const float th = tanhf(0.5f * lam * un);
    const float sc = th / un;
    const float sec0 = sc * o0, sec1 = sc * o1;
    const float xy = wred(a0 * sec0 + a1 * sec1);
    const float y2 = wred(sec0 * sec0 + sec1 * sec1);
    const float A = 1.f + 2.f * xy + y2;
    const float Bc = 1.f - xx2;
    const float den = fmaxf(1.f + 2.f * xy + xx2 * y2, 1e-15f);
    const float inv = 1.f / den;
    float r0 = (A * a0 + Bc * sec0) * inv;
    float r1 = (A * a1 + Bc * sec1) * inv;
    const float nrm = fmaxf(sqrtf(wred(r0 * r0 + r1 * r1)), 1e-15f);
    if (nrm > 0.996f) { const float s = 0.996f / nrm; r0 *= s; r1 *= s; }
    float* orow = out + (size_t)gr_ * 64;
    orow[lane] = r0; orow[lane + 32] = r1;
  }
}

extern "C" void kernel_launch(void* const* d_in, const int* in_sizes, int n_in,
                              void* d_out, int out_size)
{
  const float* x      = (const float*)d_in[0];
  const int*   mask   = (const int*)d_in[1];
  const float* att_w1 = (const float*)d_in[2];
  const float* att_b1 = (const float*)d_in[3];
  const float* att_w2 = (const float*)d_in[4];
  const float* att_b2 = (const float*)d_in[5];
  const float* mlp_w1 = (const float*)d_in[6];
  const float* mlp_b1 = (const float*)d_in[7];
  const float* mlp_w2 = (const float*)d_in[8];
  const float* mlp_b2 = (const float*)d_in[9];
  float* out = (float*)d_out;

  k_pre<<<GRAM_BLOCKS + ROW_BLOCKS, 256>>>(x, att_w1, att_b1);
  k_main<<<Bb * (Nn / 4), 256>>>(x, mask, att_w2, att_b2,
                                 mlp_w1, mlp_b1, mlp_w2, mlp_b2, out);
}